// round 8
// baseline (speedup 1.0000x reference)
#include <cuda_runtime.h>
#include <cuda_fp16.h>
#include <math.h>
#include <stdint.h>

typedef unsigned long long ull;

#define NJ 52
#define NV 6890
#define NB 10
#define NP 459            // (NJ-1)*9
#define BATCH 512
#define R3 20670          // NV*3
#define NVP 6912          // padded NV for transposed weights
#define SK_BT 2           // batches per block in skin
#define KC 480            // padded K: 459 pose + 10 betas + 1 vt + 10 pad
#define NKS (KC/16)       // 30 k-steps
#define MROWS 20736       // 162*128 padded rows

__constant__ int c_parents[NJ] = {
    -1,0,0,0,1,2,3,4,5,6,7,8,9,9,9,12,13,14,16,17,18,19,20,22,23,20,25,26,
    20,28,29,20,31,32,20,34,35,21,37,38,21,40,41,21,43,44,21,46,47,21,49,50};

// ---- scratch (__device__ globals: allocation-free) ----
__device__ __align__(16) __half d_RHi[(size_t)MROWS * KC];  // dirs hi (~20MB)
__device__ __align__(16) __half d_RLo[(size_t)MROWS * KC];  // dirs lo
__device__ __align__(16) __half d_PH [(size_t)BATCH * KC];  // pose single fp16
__device__ float d_wT [NJ * NVP];        // weights^T, padded
__device__ float d_A2 [BATCH * NJ * 12]; // A2 rows 0..2 (3x4 per joint)
__device__ float d_J0 [NJ * 3];
__device__ float d_Jsh[NJ * 3 * NB];

// ---------------- f32x2 packed-math helpers (skin kernel) -------------------
__device__ __forceinline__ ull fma2(ull a, ull b, ull c) {
    ull d;
    asm("fma.rn.f32x2 %0, %1, %2, %3;" : "=l"(d) : "l"(a), "l"(b), "l"(c));
    return d;
}
__device__ __forceinline__ ull splat2(float x) {
    ull r;
    asm("mov.b64 %0, {%1, %2};" : "=l"(r) : "f"(x), "f"(x));
    return r;
}
__device__ __forceinline__ float2 unpack2(ull u) {
    float2 f;
    asm("mov.b64 {%0, %1}, %2;" : "=f"(f.x), "=f"(f.y) : "l"(u));
    return f;
}

// ---------------- mma.sync / ldmatrix / cp.async helpers (plain sm_103) -----
__device__ __forceinline__ uint32_t smem_u32(const void* p) {
    uint32_t a;
    asm("{ .reg .u64 t; cvta.to.shared.u64 t, %1; cvt.u32.u64 %0, t; }" : "=r"(a) : "l"(p));
    return a;
}
__device__ __forceinline__ void ldsm4(uint32_t* r, uint32_t addr) {
    asm volatile("ldmatrix.sync.aligned.m8n8.x4.shared.b16 {%0,%1,%2,%3}, [%4];"
                 : "=r"(r[0]), "=r"(r[1]), "=r"(r[2]), "=r"(r[3]) : "r"(addr));
}
__device__ __forceinline__ void mma16816(float* d, const uint32_t* a, const uint32_t* b) {
    asm volatile("mma.sync.aligned.m16n8k16.row.col.f32.f16.f16.f32 "
                 "{%0,%1,%2,%3}, {%4,%5,%6,%7}, {%8,%9}, {%0,%1,%2,%3};"
                 : "+f"(d[0]), "+f"(d[1]), "+f"(d[2]), "+f"(d[3])
                 : "r"(a[0]), "r"(a[1]), "r"(a[2]), "r"(a[3]), "r"(b[0]), "r"(b[1]));
}
__device__ __forceinline__ void cpasync16(uint32_t dst, const void* src) {
    asm volatile("cp.async.cg.shared.global [%0], [%1], 16;" :: "r"(dst), "l"(src));
}
__device__ __forceinline__ void cpcommit() {
    asm volatile("cp.async.commit_group;" ::: "memory");
}
__device__ __forceinline__ void cpwait1() {
    asm volatile("cp.async.wait_group 1;" ::: "memory");
}
__device__ __forceinline__ void cpwait0() {
    asm volatile("cp.async.wait_group 0;" ::: "memory");
}

// ---------------------------------------------------------------------------
// convert R_cat = [posedirs | shapedirs | v_template | 0] -> fp16 hi/lo
// ---------------------------------------------------------------------------
__global__ void convertR_kernel(const float* __restrict__ pd,
                                const float* __restrict__ sd,
                                const float* __restrict__ vt) {
    int gid = blockIdx.x * 256 + threadIdx.x;   // MROWS*60 threads
    int r  = gid / 60;
    int k0 = (gid % 60) * 8;
    if (r >= MROWS) return;
    __align__(16) __half h[8];
    __align__(16) __half l[8];
#pragma unroll
    for (int t = 0; t < 8; t++) {
        int k = k0 + t;
        float x = 0.f;
        if (r < R3) {
            if (k < NP)            x = pd[(size_t)r * NP + k];
            else if (k < NP + NB)  x = sd[(size_t)r * NB + (k - NP)];
            else if (k == NP + NB) x = vt[r];
        }
        __half hh = __float2half(x);
        h[t] = hh;
        l[t] = __float2half(x - __half2float(hh));
    }
    size_t o = (size_t)r * KC + k0;
    *(uint4*)&d_RHi[o] = *(uint4*)h;
    *(uint4*)&d_RLo[o] = *(uint4*)l;
}

// ---------------------------------------------------------------------------
// fold J_regressor: J0 = Jreg @ v_template, Jsh = Jreg @ shapedirs
// ---------------------------------------------------------------------------
__global__ void jreg_kernel(const float* __restrict__ Jreg,
                            const float* __restrict__ vt,
                            const float* __restrict__ sd) {
    int j = blockIdx.x;
    int tid = threadIdx.x;          // 256 threads
    float acc[33];
#pragma unroll
    for (int o = 0; o < 33; o++) acc[o] = 0.f;
    for (int v = tid; v < NV; v += 256) {
        float jr = Jreg[(size_t)j * NV + v];
#pragma unroll
        for (int k = 0; k < 3; k++) {
            acc[k] += jr * vt[v * 3 + k];
#pragma unroll
            for (int q = 0; q < NB; q++)
                acc[3 + k * NB + q] += jr * sd[(size_t)(v * 3 + k) * NB + q];
        }
    }
    __shared__ float red[256];
    for (int o = 0; o < 33; o++) {
        red[tid] = acc[o];
        __syncthreads();
        for (int s = 128; s > 0; s >>= 1) {
            if (tid < s) red[tid] += red[tid + s];
            __syncthreads();
        }
        if (tid == 0) {
            if (o < 3) d_J0[j * 3 + o] = red[0];
            else       d_Jsh[j * 30 + (o - 3)] = red[0];
        }
        __syncthreads();
    }
}

// ---------------------------------------------------------------------------
// per-batch: rodrigues, P (fp16), th_j, kinematic chain, A2, th_jtr
// ---------------------------------------------------------------------------
__global__ void pose_kernel(const float* __restrict__ pose,
                            const float* __restrict__ betas,
                            const float* __restrict__ trans,
                            float* __restrict__ out_jtr) {
    int b = blockIdx.x;
    int tid = threadIdx.x;          // 64 threads
    __shared__ float rot_s[NJ][9];
    __shared__ float j_s[NJ][3];
    __shared__ float A_s[NJ][12];
    __shared__ float bet_s[NB];

    if (tid < NB) bet_s[tid] = betas[b * NB + tid];
    if (tid < NJ) {
        float x = pose[b * NJ * 3 + tid * 3 + 0];
        float y = pose[b * NJ * 3 + tid * 3 + 1];
        float z = pose[b * NJ * 3 + tid * 3 + 2];
        float th = sqrtf(x * x + y * y + z * z + 1e-8f);
        float inv = 1.f / th;
        float kx = x * inv, ky = y * inv, kz = z * inv;
        float s = sinf(th), c = cosf(th), oc = 1.f - c;
        rot_s[tid][0] = c + oc * kx * kx;
        rot_s[tid][1] = -s * kz + oc * kx * ky;
        rot_s[tid][2] =  s * ky + oc * kx * kz;
        rot_s[tid][3] =  s * kz + oc * ky * kx;
        rot_s[tid][4] = c + oc * ky * ky;
        rot_s[tid][5] = -s * kx + oc * ky * kz;
        rot_s[tid][6] = -s * ky + oc * kz * kx;
        rot_s[tid][7] =  s * kx + oc * kz * ky;
        rot_s[tid][8] = c + oc * kz * kz;
    }
    __syncthreads();

    // th_j = J0 + Jsh @ betas
    for (int idx = tid; idx < NJ * 3; idx += 64) {
        int j = idx / 3, k = idx % 3;
        float v = d_J0[idx];
#pragma unroll
        for (int q = 0; q < NB; q++)
            v += d_Jsh[j * 30 + k * NB + q] * bet_s[q];
        j_s[j][k] = v;
    }
    // P = [pose_map | betas | 1 | 0] as fp16
    for (int k = tid; k < KC; k += 64) {
        float x;
        if (k < NP) {
            int j = k / 9 + 1, e = k % 9;
            float iv = (e == 0 || e == 4 || e == 8) ? 1.f : 0.f;
            x = rot_s[j][e] - iv;
        } else if (k < NP + NB) {
            x = bet_s[k - NP];
        } else if (k == NP + NB) {
            x = 1.f;
        } else {
            x = 0.f;
        }
        d_PH[(size_t)b * KC + k] = __float2half(x);
    }
    __syncthreads();

    if (tid == 0) {
#pragma unroll
        for (int m = 0; m < 3; m++) {
#pragma unroll
            for (int n = 0; n < 3; n++) A_s[0][m * 4 + n] = rot_s[0][m * 3 + n];
            A_s[0][m * 4 + 3] = j_s[0][m];
        }
        for (int i = 1; i < NJ; i++) {
            int p = c_parents[i];
            float t0 = j_s[i][0] - j_s[p][0];
            float t1 = j_s[i][1] - j_s[p][1];
            float t2 = j_s[i][2] - j_s[p][2];
#pragma unroll
            for (int m = 0; m < 3; m++) {
                float r0 = A_s[p][m * 4 + 0], r1 = A_s[p][m * 4 + 1], r2 = A_s[p][m * 4 + 2];
#pragma unroll
                for (int n = 0; n < 3; n++)
                    A_s[i][m * 4 + n] = r0 * rot_s[i][0 * 3 + n] + r1 * rot_s[i][1 * 3 + n] + r2 * rot_s[i][2 * 3 + n];
                A_s[i][m * 4 + 3] = r0 * t0 + r1 * t1 + r2 * t2 + A_s[p][m * 4 + 3];
            }
        }
    }
    __syncthreads();

    for (int idx = tid; idx < NJ * 3; idx += 64) {
        int j = idx / 3, m = idx % 3;
        float r0 = A_s[j][m * 4 + 0], r1 = A_s[j][m * 4 + 1], r2 = A_s[j][m * 4 + 2];
        float t  = A_s[j][m * 4 + 3];
        float tmp = r0 * j_s[j][0] + r1 * j_s[j][1] + r2 * j_s[j][2];
        float* a2 = &d_A2[((size_t)b * NJ + j) * 12 + m * 4];
        a2[0] = r0; a2[1] = r1; a2[2] = r2; a2[3] = t - tmp;
        out_jtr[(size_t)b * NJ * 3 + j * 3 + m] = t + trans[b * 3 + m];
    }
}

// ---------------------------------------------------------------------------
// naked GEMM via mma.sync fp16x2: C = P_f16 * (Rhi + Rlo)
// block tile 128 batches x 128 rows; 8 warps as 2(m) x 4(n); 2-stage cp.async
// ---------------------------------------------------------------------------
__global__ __launch_bounds__(256) void mma_naked_kernel(float* __restrict__ out_vposed,
                                                        float* __restrict__ out_naked) {
    // row stride 24 half (48B) -> conflict-free ldmatrix
    __shared__ __align__(16) __half sA [2][128 * 24];   // P (single fp16)
    __shared__ __align__(16) __half sBH[2][128 * 24];   // R hi
    __shared__ __align__(16) __half sBL[2][128 * 24];   // R lo

    const int tid  = threadIdx.x;
    const int wid  = tid >> 5;
    const int lane = tid & 31;
    const int wm = wid & 1;      // warp m index (0..1)
    const int wn = wid >> 1;     // warp n index (0..3)
    const int r0 = blockIdx.x * 128;   // dirs rows
    const int b0 = blockIdx.y * 128;   // batches
    const uint32_t STG = 128 * 24 * 2; // 6144 bytes per buffer stage

    // cp.async: thread covers one (row, 16B-chunk) per buffer
    const int crow = tid >> 1;         // 0..127
    const int cch  = tid & 1;
    const uint32_t dstoff = (uint32_t)(crow * 48 + cch * 16);
    uint32_t dA  = smem_u32(sA)  + dstoff;
    uint32_t dBH = smem_u32(sBH) + dstoff;
    uint32_t dBL = smem_u32(sBL) + dstoff;
    const __half* gP  = d_PH  + (size_t)(b0 + crow) * KC + cch * 8;
    const __half* gRh = d_RHi + (size_t)(r0 + crow) * KC + cch * 8;
    const __half* gRl = d_RLo + (size_t)(r0 + crow) * KC + cch * 8;

    // ldmatrix per-lane byte offsets within a stage
    const uint32_t offA = (uint32_t)((wm * 64 + (lane & 15)) * 48 + (lane >> 4) * 16);
    const uint32_t offB = (uint32_t)((wn * 32 + (lane & 7) + ((lane >> 4) & 1) * 8) * 48
                                     + ((lane >> 3) & 1) * 16);
    uint32_t aB  = smem_u32(sA)  + offA;
    uint32_t bHB = smem_u32(sBH) + offB;
    uint32_t bLB = smem_u32(sBL) + offB;

    float d[4][4][4];   // [mtile][n8-tile][frag]
#pragma unroll
    for (int i = 0; i < 4; i++)
#pragma unroll
        for (int j = 0; j < 4; j++)
#pragma unroll
            for (int k = 0; k < 4; k++) d[i][j][k] = 0.f;

    // prologue: stage 0
    cpasync16(dA,  gP);
    cpasync16(dBH, gRh);
    cpasync16(dBL, gRl);
    cpcommit();

    for (int ks = 0; ks < NKS; ks++) {
        if (ks + 1 < NKS) {
            uint32_t so = ((ks + 1) & 1) * STG;
            int koff = (ks + 1) * 16;
            cpasync16(dA  + so, gP  + koff);
            cpasync16(dBH + so, gRh + koff);
            cpasync16(dBL + so, gRl + koff);
            cpcommit();
            cpwait1();
        } else {
            cpwait0();
        }
        __syncthreads();

        uint32_t st = (ks & 1) * STG;
        uint32_t bh[2][4], bl[2][4];
        ldsm4(bh[0], bHB + st);
        ldsm4(bh[1], bHB + st + 768);
        ldsm4(bl[0], bLB + st);
        ldsm4(bl[1], bLB + st + 768);
#pragma unroll
        for (int mi = 0; mi < 4; mi++) {
            uint32_t a[4];
            ldsm4(a, aB + st + mi * 768);
#pragma unroll
            for (int g = 0; g < 2; g++) {
                mma16816(d[mi][2 * g],     a, bh[g]);
                mma16816(d[mi][2 * g],     a, bl[g]);
                mma16816(d[mi][2 * g + 1], a, bh[g] + 2);
                mma16816(d[mi][2 * g + 1], a, bl[g] + 2);
            }
        }
        __syncthreads();
    }

    // epilogue: lane frag (c0,c1)->(m,n), (c2,c3)->(m+8,n)
    int mbase = b0 + wm * 64 + (lane >> 2);
    int nbase = r0 + wn * 32 + (lane & 3) * 2;
#pragma unroll
    for (int mi = 0; mi < 4; mi++) {
        int m = mbase + mi * 16;
#pragma unroll
        for (int t = 0; t < 4; t++) {
            int n = nbase + t * 8;
            if (n < R3) {
                size_t o1 = (size_t)m * R3 + n;
                size_t o2 = (size_t)(m + 8) * R3 + n;
                float2 v01 = make_float2(d[mi][t][0], d[mi][t][1]);
                float2 v23 = make_float2(d[mi][t][2], d[mi][t][3]);
                *(float2*)(out_vposed + o1) = v01;
                *(float2*)(out_naked  + o1) = v01;
                *(float2*)(out_vposed + o2) = v23;
                *(float2*)(out_naked  + o2) = v23;
            }
        }
    }
}

// ---------------------------------------------------------------------------
// transpose weights (NV x NJ) -> (NJ x NVP)
// ---------------------------------------------------------------------------
__global__ void transpose_kernel(const float* __restrict__ in, float* __restrict__ out,
                                 int M, int N, int ldOut) {
    __shared__ float tile[32][33];
    int c0 = blockIdx.x * 32;
    int r0 = blockIdx.y * 32;
    int tx = threadIdx.x, ty = threadIdx.y;   // block (32,8)
#pragma unroll
    for (int i = 0; i < 32; i += 8) {
        int r = r0 + ty + i, c = c0 + tx;
        tile[ty + i][tx] = (r < M && c < N) ? in[(size_t)r * N + c] : 0.f;
    }
    __syncthreads();
#pragma unroll
    for (int i = 0; i < 32; i += 8) {
        int c = c0 + ty + i, r = r0 + tx;
        if (c < N && r < ldOut)
            out[(size_t)c * ldOut + r] = tile[tx][ty + i];
    }
}

// ---------------------------------------------------------------------------
// skinning: 4 verts x 2 batches per thread, f32x2 math, float2 I/O
// ---------------------------------------------------------------------------
__global__ __launch_bounds__(128) void skin_kernel(const float* __restrict__ trans,
                                                   const float* __restrict__ naked_in,
                                                   float* __restrict__ out_verts) {
    __shared__ __align__(16) float A2_s[SK_BT][NJ * 12];
    int b0 = blockIdx.y * SK_BT;
    int tid = threadIdx.x;

    for (int i = tid; i < SK_BT * NJ * 12; i += 128) {
        int bb = i / (NJ * 12), e = i % (NJ * 12);
        A2_s[bb][e] = d_A2[(size_t)(b0 + bb) * NJ * 12 + e];
    }
    __syncthreads();

    int v0 = (blockIdx.x * 128 + tid) * 4;
    if (v0 >= NV) return;

    ull acc[SK_BT][4][6];
#pragma unroll
    for (int b = 0; b < SK_BT; b++)
#pragma unroll
        for (int vi = 0; vi < 4; vi++)
#pragma unroll
            for (int e = 0; e < 6; e++) acc[b][vi][e] = 0ULL;

    for (int j = 0; j < NJ; j++) {
        float4 w = *(const float4*)&d_wT[(size_t)j * NVP + v0];
        ull ws[4] = {splat2(w.x), splat2(w.y), splat2(w.z), splat2(w.w)};
#pragma unroll
        for (int b = 0; b < SK_BT; b++) {
            const ull* a2p = (const ull*)&A2_s[b][j * 12];
#pragma unroll
            for (int e = 0; e < 6; e++) {
                ull av = a2p[e];
                acc[b][0][e] = fma2(ws[0], av, acc[b][0][e]);
                acc[b][1][e] = fma2(ws[1], av, acc[b][1][e]);
                acc[b][2][e] = fma2(ws[2], av, acc[b][2][e]);
                acc[b][3][e] = fma2(ws[3], av, acc[b][3][e]);
            }
        }
    }

    bool full = (v0 + 3 < NV);
#pragma unroll
    for (int b = 0; b < SK_BT; b++) {
        int bglob = b0 + b;
        float tx = trans[bglob * 3 + 0], ty = trans[bglob * 3 + 1], tz = trans[bglob * 3 + 2];
        size_t base = (size_t)bglob * R3 + (size_t)v0 * 3;   // even -> float2-safe
        float o[12], nk[12];
        if (full) {
#pragma unroll
            for (int c = 0; c < 6; c++) {
                float2 t = *(const float2*)(naked_in + base + c * 2);
                nk[c * 2] = t.x; nk[c * 2 + 1] = t.y;
            }
        } else {
            int cnt = (NV - v0) * 3;
            for (int i = 0; i < 12; i++) nk[i] = (i < cnt) ? naked_in[base + i] : 0.f;
        }
#pragma unroll
        for (int vi = 0; vi < 4; vi++) {
            float nx = nk[vi * 3 + 0], ny = nk[vi * 3 + 1], nz = nk[vi * 3 + 2];
            float2 t01 = unpack2(acc[b][vi][0]);
            float2 t23 = unpack2(acc[b][vi][1]);
            float2 t45 = unpack2(acc[b][vi][2]);
            float2 t67 = unpack2(acc[b][vi][3]);
            float2 t89 = unpack2(acc[b][vi][4]);
            float2 tab = unpack2(acc[b][vi][5]);
            o[vi * 3 + 0] = t01.x * nx + t01.y * ny + t23.x * nz + t23.y + tx;
            o[vi * 3 + 1] = t45.x * nx + t45.y * ny + t67.x * nz + t67.y + ty;
            o[vi * 3 + 2] = t89.x * nx + t89.y * ny + tab.x * nz + tab.y + tz;
        }
        if (full) {
#pragma unroll
            for (int c = 0; c < 6; c++)
                *(float2*)(out_verts + base + c * 2) = make_float2(o[c * 2], o[c * 2 + 1]);
        } else {
            int cnt = (NV - v0) * 3;
            for (int i = 0; i < 12 && i < cnt; i++) out_verts[base + i] = o[i];
        }
    }
}

// ---------------------------------------------------------------------------
extern "C" void kernel_launch(void* const* d_in, const int* in_sizes, int n_in,
                              void* d_out, int out_size) {
    (void)in_sizes; (void)n_in; (void)out_size;
    const float* pose  = (const float*)d_in[0];
    const float* betas = (const float*)d_in[1];
    const float* trans = (const float*)d_in[2];
    const float* vt    = (const float*)d_in[3];
    const float* sd    = (const float*)d_in[4];
    const float* pd    = (const float*)d_in[5];
    const float* Jreg  = (const float*)d_in[6];
    const float* wgt   = (const float*)d_in[7];

    float* out        = (float*)d_out;
    float* out_verts  = out;
    float* out_jtr    = out_verts + (size_t)BATCH * R3;
    float* out_vposed = out_jtr   + (size_t)BATCH * NJ * 3;
    float* out_naked  = out_vposed + (size_t)BATCH * R3;

    void* p_wT;
    cudaGetSymbolAddress(&p_wT, d_wT);

    // side streams + events, created once (host objects, no device memory)
    static cudaStream_t s1 = nullptr, s2 = nullptr;
    static cudaEvent_t e0 = nullptr, e1 = nullptr, e2 = nullptr;
    if (!s1) {
        cudaStreamCreateWithFlags(&s1, cudaStreamNonBlocking);
        cudaStreamCreateWithFlags(&s2, cudaStreamNonBlocking);
        cudaEventCreateWithFlags(&e0, cudaEventDisableTiming);
        cudaEventCreateWithFlags(&e1, cudaEventDisableTiming);
        cudaEventCreateWithFlags(&e2, cudaEventDisableTiming);
    }

    cudaEventRecord(e0, 0);

    int convThreads = MROWS * 60;
    convertR_kernel<<<(convThreads + 255) / 256, 256>>>(pd, sd, vt);          // launch 0 (main)

    cudaStreamWaitEvent(s1, e0, 0);
    jreg_kernel<<<NJ, 256, 0, s1>>>(Jreg, vt, sd);                            // launch 1 (s1)
    pose_kernel<<<BATCH, 64, 0, s1>>>(pose, betas, trans, out_jtr);           // launch 2 (s1)
    cudaEventRecord(e1, s1);

    cudaStreamWaitEvent(0, e1, 0);
    mma_naked_kernel<<<dim3(162, 4), 256>>>(out_vposed, out_naked);           // launch 3 (main, profiled)

    cudaStreamWaitEvent(s2, e0, 0);
    dim3 tb(32, 8);
    transpose_kernel<<<dim3((NJ + 31) / 32, (NV + 31) / 32), tb, 0, s2>>>(wgt, (float*)p_wT, NV, NJ, NVP); // launch 4 (s2)
    cudaEventRecord(e2, s2);

    cudaStreamWaitEvent(0, e2, 0);
    skin_kernel<<<dim3((NV / 4 + 127) / 128, BATCH / SK_BT), 128>>>(trans, out_naked, out_verts);          // launch 5 (main)
}

// round 9
// speedup vs baseline: 1.6589x; 1.6589x over previous
#include <cuda_runtime.h>
#include <cuda_fp16.h>
#include <math.h>
#include <stdint.h>

typedef unsigned long long ull;

#define NJ 52
#define NV 6890
#define NB 10
#define NP 459            // (NJ-1)*9
#define BATCH 512
#define R3 20670          // NV*3
#define NVP 6912          // padded NV for transposed weights
#define SK_BT 2           // batches per block in skin
#define KC 496            // 459 pose | pad | 11 hi | pad | 11 lo | pad
#define NKS (KC/16)       // 31 k-steps
#define MROWS 20736       // 162*128 padded rows
#define HI0 464
#define HI1 475
#define LO0 480
#define LO1 491

__constant__ int c_parents[NJ] = {
    -1,0,0,0,1,2,3,4,5,6,7,8,9,9,9,12,13,14,16,17,18,19,20,22,23,20,25,26,
    20,28,29,20,31,32,20,34,35,21,37,38,21,40,41,21,43,44,21,46,47,21,49,50};

// ---- scratch (__device__ globals: allocation-free) ----
__device__ __align__(16) __half d_Rf[(size_t)MROWS * KC];  // dirs fp16 (~20MB)
__device__ __align__(16) __half d_PH[(size_t)BATCH * KC];  // batch rows fp16
__device__ float d_wT [NJ * NVP];        // weights^T, padded
__device__ float d_A2 [BATCH * NJ * 12]; // A2 rows 0..2 (3x4 per joint)
__device__ float d_J0 [NJ * 3];
__device__ float d_Jsh[NJ * 3 * NB];

// ---------------- f32x2 packed-math helpers (skin kernel) -------------------
__device__ __forceinline__ ull fma2(ull a, ull b, ull c) {
    ull d;
    asm("fma.rn.f32x2 %0, %1, %2, %3;" : "=l"(d) : "l"(a), "l"(b), "l"(c));
    return d;
}
__device__ __forceinline__ ull splat2(float x) {
    ull r;
    asm("mov.b64 %0, {%1, %2};" : "=l"(r) : "f"(x), "f"(x));
    return r;
}
__device__ __forceinline__ float2 unpack2(ull u) {
    float2 f;
    asm("mov.b64 {%0, %1}, %2;" : "=f"(f.x), "=f"(f.y) : "l"(u));
    return f;
}

// ---------------- mma.sync / ldmatrix / cp.async helpers (plain sm_103) -----
__device__ __forceinline__ uint32_t smem_u32(const void* p) {
    uint32_t a;
    asm("{ .reg .u64 t; cvta.to.shared.u64 t, %1; cvt.u32.u64 %0, t; }" : "=r"(a) : "l"(p));
    return a;
}
__device__ __forceinline__ void ldsm4(uint32_t* r, uint32_t addr) {
    asm volatile("ldmatrix.sync.aligned.m8n8.x4.shared.b16 {%0,%1,%2,%3}, [%4];"
                 : "=r"(r[0]), "=r"(r[1]), "=r"(r[2]), "=r"(r[3]) : "r"(addr));
}
__device__ __forceinline__ void mma16816(float* d, const uint32_t* a, const uint32_t* b) {
    asm volatile("mma.sync.aligned.m16n8k16.row.col.f32.f16.f16.f32 "
                 "{%0,%1,%2,%3}, {%4,%5,%6,%7}, {%8,%9}, {%0,%1,%2,%3};"
                 : "+f"(d[0]), "+f"(d[1]), "+f"(d[2]), "+f"(d[3])
                 : "r"(a[0]), "r"(a[1]), "r"(a[2]), "r"(a[3]), "r"(b[0]), "r"(b[1]));
}
__device__ __forceinline__ void cpasync16(uint32_t dst, const void* src) {
    asm volatile("cp.async.cg.shared.global [%0], [%1], 16;" :: "r"(dst), "l"(src));
}
__device__ __forceinline__ void cpcommit() {
    asm volatile("cp.async.commit_group;" ::: "memory");
}
__device__ __forceinline__ void cpwait1() {
    asm volatile("cp.async.wait_group 1;" ::: "memory");
}
__device__ __forceinline__ void cpwait0() {
    asm volatile("cp.async.wait_group 0;" ::: "memory");
}

// ---------------------------------------------------------------------------
// convert R_cat -> fp16:
// cols [0,459): posedirs ; [464,475): [shapedirs|vt] hi ; [480,491): residual lo
// ---------------------------------------------------------------------------
__global__ void convertR_kernel(const float* __restrict__ pd,
                                const float* __restrict__ sd,
                                const float* __restrict__ vt) {
    int gid = blockIdx.x * 256 + threadIdx.x;   // MROWS*62 threads
    int r  = gid / 62;
    int k0 = (gid % 62) * 8;
    if (r >= MROWS) return;
    __align__(16) __half h[8];
#pragma unroll
    for (int t = 0; t < 8; t++) {
        int k = k0 + t;
        float x = 0.f;
        if (r < R3) {
            if (k < NP) {
                x = pd[(size_t)r * NP + k];
            } else if (k >= HI0 && k < HI1) {
                int i = k - HI0;
                x = (i < NB) ? sd[(size_t)r * NB + i] : vt[r];
            } else if (k >= LO0 && k < LO1) {
                int i = k - LO0;
                float v = (i < NB) ? sd[(size_t)r * NB + i] : vt[r];
                x = v - __half2float(__float2half(v));
            }
        }
        h[t] = __float2half(x);
    }
    size_t o = (size_t)r * KC + k0;
    *(uint4*)&d_Rf[o] = *(uint4*)h;
}

// ---------------------------------------------------------------------------
// fold J_regressor: J0 = Jreg @ v_template, Jsh = Jreg @ shapedirs
// ---------------------------------------------------------------------------
__global__ void jreg_kernel(const float* __restrict__ Jreg,
                            const float* __restrict__ vt,
                            const float* __restrict__ sd) {
    int j = blockIdx.x;
    int tid = threadIdx.x;          // 256 threads
    float acc[33];
#pragma unroll
    for (int o = 0; o < 33; o++) acc[o] = 0.f;
    for (int v = tid; v < NV; v += 256) {
        float jr = Jreg[(size_t)j * NV + v];
#pragma unroll
        for (int k = 0; k < 3; k++) {
            acc[k] += jr * vt[v * 3 + k];
#pragma unroll
            for (int q = 0; q < NB; q++)
                acc[3 + k * NB + q] += jr * sd[(size_t)(v * 3 + k) * NB + q];
        }
    }
    __shared__ float red[256];
    for (int o = 0; o < 33; o++) {
        red[tid] = acc[o];
        __syncthreads();
        for (int s = 128; s > 0; s >>= 1) {
            if (tid < s) red[tid] += red[tid + s];
            __syncthreads();
        }
        if (tid == 0) {
            if (o < 3) d_J0[j * 3 + o] = red[0];
            else       d_Jsh[j * 30 + (o - 3)] = red[0];
        }
        __syncthreads();
    }
}

// ---------------------------------------------------------------------------
// per-batch: rodrigues, P (fp16), th_j, kinematic chain, A2, th_jtr
// ---------------------------------------------------------------------------
__global__ void pose_kernel(const float* __restrict__ pose,
                            const float* __restrict__ betas,
                            const float* __restrict__ trans,
                            float* __restrict__ out_jtr) {
    int b = blockIdx.x;
    int tid = threadIdx.x;          // 64 threads
    __shared__ float rot_s[NJ][9];
    __shared__ float j_s[NJ][3];
    __shared__ float A_s[NJ][12];
    __shared__ float bet_s[NB];

    if (tid < NB) bet_s[tid] = betas[b * NB + tid];
    if (tid < NJ) {
        float x = pose[b * NJ * 3 + tid * 3 + 0];
        float y = pose[b * NJ * 3 + tid * 3 + 1];
        float z = pose[b * NJ * 3 + tid * 3 + 2];
        float th = sqrtf(x * x + y * y + z * z + 1e-8f);
        float inv = 1.f / th;
        float kx = x * inv, ky = y * inv, kz = z * inv;
        float s = sinf(th), c = cosf(th), oc = 1.f - c;
        rot_s[tid][0] = c + oc * kx * kx;
        rot_s[tid][1] = -s * kz + oc * kx * ky;
        rot_s[tid][2] =  s * ky + oc * kx * kz;
        rot_s[tid][3] =  s * kz + oc * ky * kx;
        rot_s[tid][4] = c + oc * ky * ky;
        rot_s[tid][5] = -s * kx + oc * ky * kz;
        rot_s[tid][6] = -s * ky + oc * kz * kx;
        rot_s[tid][7] =  s * kx + oc * kz * ky;
        rot_s[tid][8] = c + oc * kz * kz;
    }
    __syncthreads();

    // th_j = J0 + Jsh @ betas
    for (int idx = tid; idx < NJ * 3; idx += 64) {
        int j = idx / 3, k = idx % 3;
        float v = d_J0[idx];
#pragma unroll
        for (int q = 0; q < NB; q++)
            v += d_Jsh[j * 30 + k * NB + q] * bet_s[q];
        j_s[j][k] = v;
    }
    // P = [pose_map | 0 | betas,1 (hi cols) | 0 | betas,1 (lo cols) | 0] fp16
    for (int k = tid; k < KC; k += 64) {
        float x = 0.f;
        if (k < NP) {
            int j = k / 9 + 1, e = k % 9;
            float iv = (e == 0 || e == 4 || e == 8) ? 1.f : 0.f;
            x = rot_s[j][e] - iv;
        } else if (k >= HI0 && k < HI1) {
            int i = k - HI0;
            x = (i < NB) ? bet_s[i] : 1.f;
        } else if (k >= LO0 && k < LO1) {
            int i = k - LO0;
            x = (i < NB) ? bet_s[i] : 1.f;
        }
        d_PH[(size_t)b * KC + k] = __float2half(x);
    }
    __syncthreads();

    if (tid == 0) {
#pragma unroll
        for (int m = 0; m < 3; m++) {
#pragma unroll
            for (int n = 0; n < 3; n++) A_s[0][m * 4 + n] = rot_s[0][m * 3 + n];
            A_s[0][m * 4 + 3] = j_s[0][m];
        }
        for (int i = 1; i < NJ; i++) {
            int p = c_parents[i];
            float t0 = j_s[i][0] - j_s[p][0];
            float t1 = j_s[i][1] - j_s[p][1];
            float t2 = j_s[i][2] - j_s[p][2];
#pragma unroll
            for (int m = 0; m < 3; m++) {
                float r0 = A_s[p][m * 4 + 0], r1 = A_s[p][m * 4 + 1], r2 = A_s[p][m * 4 + 2];
#pragma unroll
                for (int n = 0; n < 3; n++)
                    A_s[i][m * 4 + n] = r0 * rot_s[i][0 * 3 + n] + r1 * rot_s[i][1 * 3 + n] + r2 * rot_s[i][2 * 3 + n];
                A_s[i][m * 4 + 3] = r0 * t0 + r1 * t1 + r2 * t2 + A_s[p][m * 4 + 3];
            }
        }
    }
    __syncthreads();

    for (int idx = tid; idx < NJ * 3; idx += 64) {
        int j = idx / 3, m = idx % 3;
        float r0 = A_s[j][m * 4 + 0], r1 = A_s[j][m * 4 + 1], r2 = A_s[j][m * 4 + 2];
        float t  = A_s[j][m * 4 + 3];
        float tmp = r0 * j_s[j][0] + r1 * j_s[j][1] + r2 * j_s[j][2];
        float* a2 = &d_A2[((size_t)b * NJ + j) * 12 + m * 4];
        a2[0] = r0; a2[1] = r1; a2[2] = r2; a2[3] = t - tmp;
        out_jtr[(size_t)b * NJ * 3 + j * 3 + m] = t + trans[b * 3 + m];
    }
}

// ---------------------------------------------------------------------------
// naked GEMM via mma.sync fp16 single-product: block tile 128 x 128
// 256 threads / 8 warps as 2(m) x 4(n); 2-stage cp.async; 16 HMMA/warp/kstep
// ---------------------------------------------------------------------------
__global__ __launch_bounds__(256) void mma_naked_kernel(float* __restrict__ out_vposed,
                                                        float* __restrict__ out_naked) {
    __shared__ __align__(16) __half sA[2][128 * 24];   // P rows
    __shared__ __align__(16) __half sB[2][128 * 24];   // R rows

    const int tid  = threadIdx.x;
    const int wid  = tid >> 5;
    const int lane = tid & 31;
    const int wm = wid & 1;      // warp m index (0..1)
    const int wn = wid >> 1;     // warp n index (0..3)
    const int r0 = blockIdx.x * 128;   // dirs rows
    const int b0 = blockIdx.y * 128;   // batches
    const uint32_t STG = 128 * 24 * 2; // 6144 bytes per stage

    // cp.async: thread covers one (row, 16B-chunk) per buffer
    const int crow = tid >> 1;         // 0..127
    const int cch  = tid & 1;
    const uint32_t dstoff = (uint32_t)(crow * 48 + cch * 16);
    uint32_t dA = smem_u32(sA) + dstoff;
    uint32_t dB = smem_u32(sB) + dstoff;
    const __half* gP = d_PH + (size_t)(b0 + crow) * KC + cch * 8;
    const __half* gR = d_Rf + (size_t)(r0 + crow) * KC + cch * 8;

    // ldmatrix per-lane byte offsets within a stage
    const uint32_t offA = (uint32_t)((wm * 64 + (lane & 15)) * 48 + (lane >> 4) * 16);
    const uint32_t offB = (uint32_t)((wn * 32 + (lane & 7) + ((lane >> 4) & 1) * 8) * 48
                                     + ((lane >> 3) & 1) * 16);
    uint32_t aB = smem_u32(sA) + offA;
    uint32_t bB = smem_u32(sB) + offB;

    float d[4][4][4];   // [mtile][n8-tile][frag]
#pragma unroll
    for (int i = 0; i < 4; i++)
#pragma unroll
        for (int j = 0; j < 4; j++)
#pragma unroll
            for (int k = 0; k < 4; k++) d[i][j][k] = 0.f;

    // prologue: stage 0
    cpasync16(dA, gP);
    cpasync16(dB, gR);
    cpcommit();

    for (int ks = 0; ks < NKS; ks++) {
        if (ks + 1 < NKS) {
            uint32_t so = ((ks + 1) & 1) * STG;
            int koff = (ks + 1) * 16;
            cpasync16(dA + so, gP + koff);
            cpasync16(dB + so, gR + koff);
            cpcommit();
            cpwait1();
        } else {
            cpwait0();
        }
        __syncthreads();

        uint32_t st = (ks & 1) * STG;
        uint32_t bb[2][4];
        ldsm4(bb[0], bB + st);
        ldsm4(bb[1], bB + st + 768);
#pragma unroll
        for (int mi = 0; mi < 4; mi++) {
            uint32_t a[4];
            ldsm4(a, aB + st + mi * 768);
            mma16816(d[mi][0], a, bb[0]);
            mma16816(d[mi][1], a, bb[0] + 2);
            mma16816(d[mi][2], a, bb[1]);
            mma16816(d[mi][3], a, bb[1] + 2);
        }
        __syncthreads();
    }

    // epilogue: lane frag (c0,c1)->(m,n), (c2,c3)->(m+8,n)
    int mbase = b0 + wm * 64 + (lane >> 2);
    int nbase = r0 + wn * 32 + (lane & 3) * 2;
#pragma unroll
    for (int mi = 0; mi < 4; mi++) {
        int m = mbase + mi * 16;
#pragma unroll
        for (int t = 0; t < 4; t++) {
            int n = nbase + t * 8;
            if (n < R3) {
                size_t o1 = (size_t)m * R3 + n;
                size_t o2 = (size_t)(m + 8) * R3 + n;
                float2 v01 = make_float2(d[mi][t][0], d[mi][t][1]);
                float2 v23 = make_float2(d[mi][t][2], d[mi][t][3]);
                *(float2*)(out_vposed + o1) = v01;
                *(float2*)(out_naked  + o1) = v01;
                *(float2*)(out_vposed + o2) = v23;
                *(float2*)(out_naked  + o2) = v23;
            }
        }
    }
}

// ---------------------------------------------------------------------------
// transpose weights (NV x NJ) -> (NJ x NVP)
// ---------------------------------------------------------------------------
__global__ void transpose_kernel(const float* __restrict__ in, float* __restrict__ out,
                                 int M, int N, int ldOut) {
    __shared__ float tile[32][33];
    int c0 = blockIdx.x * 32;
    int r0 = blockIdx.y * 32;
    int tx = threadIdx.x, ty = threadIdx.y;   // block (32,8)
#pragma unroll
    for (int i = 0; i < 32; i += 8) {
        int r = r0 + ty + i, c = c0 + tx;
        tile[ty + i][tx] = (r < M && c < N) ? in[(size_t)r * N + c] : 0.f;
    }
    __syncthreads();
#pragma unroll
    for (int i = 0; i < 32; i += 8) {
        int c = c0 + ty + i, r = r0 + tx;
        if (c < N && r < ldOut)
            out[(size_t)c * ldOut + r] = tile[tx][ty + i];
    }
}

// ---------------------------------------------------------------------------
// skinning: 4 verts x 2 batches per thread, f32x2 math, float2 I/O
// ---------------------------------------------------------------------------
__global__ __launch_bounds__(128) void skin_kernel(const float* __restrict__ trans,
                                                   const float* __restrict__ naked_in,
                                                   float* __restrict__ out_verts) {
    __shared__ __align__(16) float A2_s[SK_BT][NJ * 12];
    int b0 = blockIdx.y * SK_BT;
    int tid = threadIdx.x;

    for (int i = tid; i < SK_BT * NJ * 12; i += 128) {
        int bb = i / (NJ * 12), e = i % (NJ * 12);
        A2_s[bb][e] = d_A2[(size_t)(b0 + bb) * NJ * 12 + e];
    }
    __syncthreads();

    int v0 = (blockIdx.x * 128 + tid) * 4;
    if (v0 >= NV) return;

    ull acc[SK_BT][4][6];
#pragma unroll
    for (int b = 0; b < SK_BT; b++)
#pragma unroll
        for (int vi = 0; vi < 4; vi++)
#pragma unroll
            for (int e = 0; e < 6; e++) acc[b][vi][e] = 0ULL;

    for (int j = 0; j < NJ; j++) {
        float4 w = *(const float4*)&d_wT[(size_t)j * NVP + v0];
        ull ws[4] = {splat2(w.x), splat2(w.y), splat2(w.z), splat2(w.w)};
#pragma unroll
        for (int b = 0; b < SK_BT; b++) {
            const ull* a2p = (const ull*)&A2_s[b][j * 12];
#pragma unroll
            for (int e = 0; e < 6; e++) {
                ull av = a2p[e];
                acc[b][0][e] = fma2(ws[0], av, acc[b][0][e]);
                acc[b][1][e] = fma2(ws[1], av, acc[b][1][e]);
                acc[b][2][e] = fma2(ws[2], av, acc[b][2][e]);
                acc[b][3][e] = fma2(ws[3], av, acc[b][3][e]);
            }
        }
    }

    bool full = (v0 + 3 < NV);
#pragma unroll
    for (int b = 0; b < SK_BT; b++) {
        int bglob = b0 + b;
        float tx = trans[bglob * 3 + 0], ty = trans[bglob * 3 + 1], tz = trans[bglob * 3 + 2];
        size_t base = (size_t)bglob * R3 + (size_t)v0 * 3;   // even -> float2-safe
        float o[12], nk[12];
        if (full) {
#pragma unroll
            for (int c = 0; c < 6; c++) {
                float2 t = *(const float2*)(naked_in + base + c * 2);
                nk[c * 2] = t.x; nk[c * 2 + 1] = t.y;
            }
        } else {
            int cnt = (NV - v0) * 3;
            for (int i = 0; i < 12; i++) nk[i] = (i < cnt) ? naked_in[base + i] : 0.f;
        }
#pragma unroll
        for (int vi = 0; vi < 4; vi++) {
            float nx = nk[vi * 3 + 0], ny = nk[vi * 3 + 1], nz = nk[vi * 3 + 2];
            float2 t01 = unpack2(acc[b][vi][0]);
            float2 t23 = unpack2(acc[b][vi][1]);
            float2 t45 = unpack2(acc[b][vi][2]);
            float2 t67 = unpack2(acc[b][vi][3]);
            float2 t89 = unpack2(acc[b][vi][4]);
            float2 tab = unpack2(acc[b][vi][5]);
            o[vi * 3 + 0] = t01.x * nx + t01.y * ny + t23.x * nz + t23.y + tx;
            o[vi * 3 + 1] = t45.x * nx + t45.y * ny + t67.x * nz + t67.y + ty;
            o[vi * 3 + 2] = t89.x * nx + t89.y * ny + tab.x * nz + tab.y + tz;
        }
        if (full) {
#pragma unroll
            for (int c = 0; c < 6; c++)
                *(float2*)(out_verts + base + c * 2) = make_float2(o[c * 2], o[c * 2 + 1]);
        } else {
            int cnt = (NV - v0) * 3;
            for (int i = 0; i < 12 && i < cnt; i++) out_verts[base + i] = o[i];
        }
    }
}

// ---------------------------------------------------------------------------
extern "C" void kernel_launch(void* const* d_in, const int* in_sizes, int n_in,
                              void* d_out, int out_size) {
    (void)in_sizes; (void)n_in; (void)out_size;
    const float* pose  = (const float*)d_in[0];
    const float* betas = (const float*)d_in[1];
    const float* trans = (const float*)d_in[2];
    const float* vt    = (const float*)d_in[3];
    const float* sd    = (const float*)d_in[4];
    const float* pd    = (const float*)d_in[5];
    const float* Jreg  = (const float*)d_in[6];
    const float* wgt   = (const float*)d_in[7];

    float* out        = (float*)d_out;
    float* out_verts  = out;
    float* out_jtr    = out_verts + (size_t)BATCH * R3;
    float* out_vposed = out_jtr   + (size_t)BATCH * NJ * 3;
    float* out_naked  = out_vposed + (size_t)BATCH * R3;

    void* p_wT;
    cudaGetSymbolAddress(&p_wT, d_wT);

    int convThreads = MROWS * 62;
    convertR_kernel<<<(convThreads + 255) / 256, 256>>>(pd, sd, vt);              // 0
    jreg_kernel<<<NJ, 256>>>(Jreg, vt, sd);                                       // 1
    pose_kernel<<<BATCH, 64>>>(pose, betas, trans, out_jtr);                      // 2
    mma_naked_kernel<<<dim3(162, 4), 256>>>(out_vposed, out_naked);               // 3
    dim3 tb(32, 8);
    transpose_kernel<<<dim3((NJ + 31) / 32, (NV + 31) / 32), tb>>>(wgt, (float*)p_wT, NV, NJ, NVP); // 4
    skin_kernel<<<dim3((NV / 4 + 127) / 128, BATCH / SK_BT), 128>>>(trans, out_naked, out_verts);   // 5
}